// round 5
// baseline (speedup 1.0000x reference)
#include <cuda_runtime.h>
#include <cuda_fp16.h>

#define NN 16
#define VV 5023
#define FF 9976
#define HH 512
#define WW 512
#define NV (NN * VV)            // 80368
#define NF (NN * FF)            // 159616
#define NPIX (NN * HH * WW)     // 4194304
#define GRID 592                // 148 SMs * 4 CTAs (co-resident, see launch_bounds)
#define TPB 256
#define NTHREADS (GRID * TPB)   // 151552

__device__ float g_pmn[GRID];
__device__ float g_pmx[GRID];
__device__ float2 g_fz8[NF];    // 8B/(image,face): z0 fp32 + (z1-z0,z2-z0) fp16x2
__device__ int g_bar_count;     // zero-init; returns to 0 after each barrier
__device__ int g_bar_gen;       // monotonically increments across replays

// Sense-reversing grid barrier. Safe: all GRID blocks are co-resident
// (regs capped at 64 by __launch_bounds__(256,4) -> 4 CTAs/SM fit the RF).
__device__ __forceinline__ void grid_barrier() {
    __syncthreads();
    if (threadIdx.x == 0) {
        __threadfence();
        int gen = *(volatile int*)&g_bar_gen;
        int t = atomicAdd(&g_bar_count, 1);
        if (t == GRID - 1) {
            g_bar_count = 0;
            __threadfence();
            *(volatile int*)&g_bar_gen = gen + 1;
        } else {
            while (*(volatile int*)&g_bar_gen == gen) __nanosleep(64);
        }
        __threadfence();
    }
    __syncthreads();
}

__global__ void __launch_bounds__(TPB, 4) fused_kernel(
    const float* __restrict__ tv,
    const int* __restrict__ faces,
    const float* __restrict__ bary,
    const int* __restrict__ p2f,
    float* __restrict__ out)
{
    const int tid = threadIdx.x;
    const int gtid = blockIdx.x * TPB + tid;
    __shared__ float smn[32], smx[32];
    __shared__ float s_m, s_R;

    // ---------------- Phase A: per-block min/max partials of tv[:,:,2] ----
    {
        float mn = __int_as_float(0x7F800000);   // +inf
        float mx = -mn;
        for (int k = gtid; k < NV; k += NTHREADS) {
            float z = __ldg(tv + 3 * k + 2);
            mn = fminf(mn, z);
            mx = fmaxf(mx, z);
        }
        #pragma unroll
        for (int o = 16; o > 0; o >>= 1) {
            mn = fminf(mn, __shfl_xor_sync(0xFFFFFFFFu, mn, o));
            mx = fmaxf(mx, __shfl_xor_sync(0xFFFFFFFFu, mx, o));
        }
        int lane = tid & 31, w = tid >> 5;
        if (lane == 0) { smn[w] = mn; smx[w] = mx; }
        __syncthreads();
        if (tid == 0) {
            float bmn = smn[0], bmx = smx[0];
            #pragma unroll
            for (int k = 1; k < TPB / 32; k++) {
                bmn = fminf(bmn, smn[k]);
                bmx = fmaxf(bmx, smx[k]);
            }
            g_pmn[blockIdx.x] = bmn;
            g_pmx[blockIdx.x] = bmx;
        }
    }
    grid_barrier();

    // ---------------- Phase B: reduce partials, build face-z table ---------
    {
        float m = __int_as_float(0x7F800000);
        float M = -m;
        for (int k = tid; k < GRID; k += TPB) {
            m = fminf(m, g_pmn[k]);
            M = fmaxf(M, g_pmx[k]);
        }
        #pragma unroll
        for (int o = 16; o > 0; o >>= 1) {
            m = fminf(m, __shfl_xor_sync(0xFFFFFFFFu, m, o));
            M = fmaxf(M, __shfl_xor_sync(0xFFFFFFFFu, M, o));
        }
        int lane = tid & 31, w = tid >> 5;
        if (lane == 0) { smn[w] = m; smx[w] = M; }
        __syncthreads();
        if (tid == 0) {
            float bm = smn[0], bM = smx[0];
            #pragma unroll
            for (int k = 1; k < TPB / 32; k++) {
                bm = fminf(bm, smn[k]);
                bM = fmaxf(bM, smx[k]);
            }
            s_m = bm;
            s_R = bM - bm;     // R = fl(M - m), reference rounding
        }
        __syncthreads();

        float m2 = s_m, R = s_R;
        for (int t = gtid; t < NF; t += NTHREADS) {
            int n = t / FF;
            int f = t - n * FF;
            int v0 = __ldg(faces + 3 * f);
            int v1 = __ldg(faces + 3 * f + 1);
            int v2 = __ldg(faces + 3 * f + 2);
            long long vb = (long long)n * VV;
            // zn = (R - fl(z - m)) / R  matches reference rounding sequence
            float zn0 = (R - (__ldg(tv + 3 * (vb + v0) + 2) - m2)) / R;
            float zn1 = (R - (__ldg(tv + 3 * (vb + v1) + 2) - m2)) / R;
            float zn2 = (R - (__ldg(tv + 3 * (vb + v2) + 2) - m2)) / R;
            __half2 d = __floats2half2_rn(zn1 - zn0, zn2 - zn0);
            float2 e;
            e.x = zn0;
            e.y = __uint_as_float(*reinterpret_cast<unsigned int*>(&d));
            g_fz8[t] = e;
        }
    }
    grid_barrier();

    // ---------------- Phase C: pixel interpolation (8 px/thread/iter) ------
    for (int u = gtid; u < NPIX / 8; u += NTHREADS) {
        long long base = (long long)u * 8;

        int4 pa = __ldcs(reinterpret_cast<const int4*>(p2f + base));
        int4 pb = __ldcs(reinterpret_cast<const int4*>(p2f + base) + 1);
        int ps[8] = {pa.x, pa.y, pa.z, pa.w, pb.x, pb.y, pb.z, pb.w};

        // Predicated gathers: invalid lanes issue NO memory transaction ->
        // ~30% fewer L1tex wavefronts (the kernel's binding resource).
        float2 e[8];
        #pragma unroll
        for (int i = 0; i < 8; i++) {
            e[i] = make_float2(0.0f, 0.0f);
            if (ps[i] >= 0) e[i] = __ldg(&g_fz8[ps[i]]);
        }

        const float4* bp = reinterpret_cast<const float4*>(bary + base * 3);
        float w[24];
        #pragma unroll
        for (int q = 0; q < 6; q++) {
            float4 v = __ldcs(bp + q);
            w[4 * q + 0] = v.x;
            w[4 * q + 1] = v.y;
            w[4 * q + 2] = v.z;
            w[4 * q + 3] = v.w;
        }

        float res[8];
        #pragma unroll
        for (int i = 0; i < 8; i++) {
            float b0 = w[3 * i], b1 = w[3 * i + 1], b2 = w[3 * i + 2];
            unsigned int db = __float_as_uint(e[i].y);
            __half2 dh = *reinterpret_cast<__half2*>(&db);
            float2 d = __half22float2(dh);
            float s = e[i].x * (b0 + b1 + b2) + b1 * d.x + b2 * d.y;
            res[i] = ps[i] >= 0 ? s : 0.0f;
        }

        float4* op = reinterpret_cast<float4*>(out + base);
        __stcs(op, make_float4(res[0], res[1], res[2], res[3]));
        __stcs(op + 1, make_float4(res[4], res[5], res[6], res[7]));
    }
}

extern "C" void kernel_launch(void* const* d_in, const int* in_sizes, int n_in,
                              void* d_out, int out_size) {
    const float* tv = nullptr;      // 241104
    const float* bary = nullptr;    // 12582912
    const int* faces = nullptr;     // 29928
    const int* p2f = nullptr;       // 4194304
    for (int i = 0; i < n_in; i++) {
        switch (in_sizes[i]) {
            case NN * VV * 3:            tv    = (const float*)d_in[i]; break;
            case NN * HH * WW * 3:       bary  = (const float*)d_in[i]; break;
            case FF * 3:                 faces = (const int*)d_in[i];   break;
            case NN * HH * WW:           p2f   = (const int*)d_in[i];   break;
        }
    }
    float* out = (float*)d_out;

    fused_kernel<<<GRID, TPB>>>(tv, faces, bary, p2f, out);
}

// round 6
// speedup vs baseline: 1.0535x; 1.0535x over previous
#include <cuda_runtime.h>
#include <cuda_fp16.h>

#define NN 16
#define VV 5023
#define FF 9976
#define HH 512
#define WW 512
#define NV (NN * VV)            // 80368
#define NF (NN * FF)            // 159616
#define NPIX (NN * HH * WW)     // 4194304
#define MMBLK 314               // minmax partial blocks (NV/256)

__device__ float g_pmn[MMBLK];
__device__ float g_pmx[MMBLK];
__device__ float2 g_fz8[NF];    // 8B/(image,face): z0 fp32 + (z1-z0,z2-z0) fp16x2

// ---------------------------------------------------------------------------
// Kernel 1: per-block min/max partials of tv[:,:,2]. Plain stores, no init.
__global__ void __launch_bounds__(256) minmax_partial_kernel(const float* __restrict__ tv) {
    int i = blockIdx.x * blockDim.x + threadIdx.x;
    float z = (i < NV) ? __ldg(tv + 3 * i + 2) : __ldg(tv + 2);
    float mn = z, mx = z;
    #pragma unroll
    for (int o = 16; o > 0; o >>= 1) {
        mn = fminf(mn, __shfl_xor_sync(0xFFFFFFFFu, mn, o));
        mx = fmaxf(mx, __shfl_xor_sync(0xFFFFFFFFu, mx, o));
    }
    __shared__ float smn[8], smx[8];
    int lane = threadIdx.x & 31, w = threadIdx.x >> 5;
    if (lane == 0) { smn[w] = mn; smx[w] = mx; }
    __syncthreads();
    if (threadIdx.x == 0) {
        float bmn = smn[0], bmx = smx[0];
        #pragma unroll
        for (int k = 1; k < 8; k++) {
            bmn = fminf(bmn, smn[k]);
            bmx = fmaxf(bmx, smx[k]);
        }
        g_pmn[blockIdx.x] = bmn;
        g_pmx[blockIdx.x] = bmx;
    }
}

// ---------------------------------------------------------------------------
// Kernel 2: each block reduces the partials (L2-hit, ~2 loads/thread), then
// builds the per-(image,face) 8B z table.
__global__ void __launch_bounds__(256) facez_kernel(const float* __restrict__ tv,
                                                    const int* __restrict__ faces) {
    float m = __int_as_float(0x7F800000);
    float M = -m;
    for (int k = threadIdx.x; k < MMBLK; k += 256) {
        m = fminf(m, g_pmn[k]);
        M = fmaxf(M, g_pmx[k]);
    }
    #pragma unroll
    for (int o = 16; o > 0; o >>= 1) {
        m = fminf(m, __shfl_xor_sync(0xFFFFFFFFu, m, o));
        M = fmaxf(M, __shfl_xor_sync(0xFFFFFFFFu, M, o));
    }
    __shared__ float smn[8], smx[8];
    __shared__ float s_m, s_R;
    int lane = threadIdx.x & 31, w = threadIdx.x >> 5;
    if (lane == 0) { smn[w] = m; smx[w] = M; }
    __syncthreads();
    if (threadIdx.x == 0) {
        float bm = smn[0], bM = smx[0];
        #pragma unroll
        for (int k = 1; k < 8; k++) {
            bm = fminf(bm, smn[k]);
            bM = fmaxf(bM, smx[k]);
        }
        s_m = bm;
        s_R = bM - bm;   // R = fl(M - m): reference rounding
    }
    __syncthreads();

    int t = blockIdx.x * blockDim.x + threadIdx.x;
    if (t >= NF) return;
    float m2 = s_m, R = s_R;
    int n = t / FF;
    int f = t - n * FF;
    int v0 = __ldg(faces + 3 * f);
    int v1 = __ldg(faces + 3 * f + 1);
    int v2 = __ldg(faces + 3 * f + 2);
    long long vb = (long long)n * VV;
    // zn = (R - fl(z - m)) / R  matches the reference rounding sequence
    float zn0 = (R - (__ldg(tv + 3 * (vb + v0) + 2) - m2)) / R;
    float zn1 = (R - (__ldg(tv + 3 * (vb + v1) + 2) - m2)) / R;
    float zn2 = (R - (__ldg(tv + 3 * (vb + v2) + 2) - m2)) / R;
    __half2 d = __floats2half2_rn(zn1 - zn0, zn2 - zn0);
    float2 e;
    e.x = zn0;
    e.y = __uint_as_float(*reinterpret_cast<unsigned int*>(&d));
    g_fz8[t] = e;
}

// ---------------------------------------------------------------------------
// Kernel 3: pixel interpolation. 8 px/thread; predicated 8B gathers (invalid
// lanes issue no LDG -> ~30% fewer L1tex wavefronts); gathers issued before
// the streaming loads; streaming uses evict-first so the 1.25MB table keeps L1.
__global__ void __launch_bounds__(256) pixel_kernel(
    const float* __restrict__ bary,
    const int* __restrict__ p2f,
    float* __restrict__ out)
{
    int t = blockIdx.x * blockDim.x + threadIdx.x;
    long long base = (long long)t * 8;
    if (base >= NPIX) return;

    int4 pa = __ldcs(reinterpret_cast<const int4*>(p2f + base));
    int4 pb = __ldcs(reinterpret_cast<const int4*>(p2f + base) + 1);
    int ps[8] = {pa.x, pa.y, pa.z, pa.w, pb.x, pb.y, pb.z, pb.w};

    // Predicated scattered gathers, all issued up front (deep LSU queue).
    float2 e[8];
    #pragma unroll
    for (int i = 0; i < 8; i++) {
        e[i] = make_float2(0.0f, 0.0f);
        if (ps[i] >= 0) e[i] = __ldg(&g_fz8[ps[i]]);
    }

    // 24 streaming bary floats (6x float4, evict-first).
    const float4* bp = reinterpret_cast<const float4*>(bary + base * 3);
    float w[24];
    #pragma unroll
    for (int q = 0; q < 6; q++) {
        float4 v = __ldcs(bp + q);
        w[4 * q + 0] = v.x;
        w[4 * q + 1] = v.y;
        w[4 * q + 2] = v.z;
        w[4 * q + 3] = v.w;
    }

    float res[8];
    #pragma unroll
    for (int i = 0; i < 8; i++) {
        float b0 = w[3 * i], b1 = w[3 * i + 1], b2 = w[3 * i + 2];
        unsigned int db = __float_as_uint(e[i].y);
        __half2 dh = *reinterpret_cast<__half2*>(&db);
        float2 d = __half22float2(dh);
        float s = e[i].x * (b0 + b1 + b2) + b1 * d.x + b2 * d.y;
        res[i] = ps[i] >= 0 ? s : 0.0f;
    }

    float4* op = reinterpret_cast<float4*>(out + base);
    __stcs(op, make_float4(res[0], res[1], res[2], res[3]));
    __stcs(op + 1, make_float4(res[4], res[5], res[6], res[7]));
}

extern "C" void kernel_launch(void* const* d_in, const int* in_sizes, int n_in,
                              void* d_out, int out_size) {
    const float* tv = nullptr;      // 241104
    const float* bary = nullptr;    // 12582912
    const int* faces = nullptr;     // 29928
    const int* p2f = nullptr;       // 4194304
    for (int i = 0; i < n_in; i++) {
        switch (in_sizes[i]) {
            case NN * VV * 3:            tv    = (const float*)d_in[i]; break;
            case NN * HH * WW * 3:       bary  = (const float*)d_in[i]; break;
            case FF * 3:                 faces = (const int*)d_in[i];   break;
            case NN * HH * WW:           p2f   = (const int*)d_in[i];   break;
        }
    }
    float* out = (float*)d_out;

    minmax_partial_kernel<<<MMBLK, 256>>>(tv);
    facez_kernel<<<(NF + 255) / 256, 256>>>(tv, faces);
    pixel_kernel<<<NPIX / 8 / 256, 256>>>(bary, p2f, out);
}

// round 8
// speedup vs baseline: 1.2901x; 1.2246x over previous
#include <cuda_runtime.h>
#include <cuda_fp16.h>

#define NN 16
#define VV 5023
#define FF 9976
#define HH 512
#define WW 512
#define NV (NN * VV)            // 80368
#define NF (NN * FF)            // 159616
#define NPIX (NN * HH * WW)     // 4194304
#define MMBLK 314               // minmax partial blocks (NV/256)

__device__ float g_pmn[MMBLK];
__device__ float g_pmx[MMBLK];
__device__ float2 g_fz8[NF];    // 8B/(image,face): z0 fp32 + (z1-z0,z2-z0) fp16x2

// Branch-free predicated 8B gather: single @p LDG.E.64.NC, no BSSY/BSYNC.
// Invalid lanes issue NO memory transaction and return (0,0).
__device__ __forceinline__ float2 gather_pred(const float2* __restrict__ tab,
                                              int idx, int valid) {
    float2 r;
    const float2* addr = tab + (valid ? idx : 0);
    asm("{\n\t"
        ".reg .pred gp;\n\t"
        "setp.ne.s32 gp, %3, 0;\n\t"
        "mov.f32 %0, 0f00000000;\n\t"
        "mov.f32 %1, 0f00000000;\n\t"
        "@gp ld.global.nc.v2.f32 {%0,%1}, [%2];\n\t"
        "}"
        : "=f"(r.x), "=f"(r.y)
        : "l"(addr), "r"(valid));
    return r;
}

// ---------------------------------------------------------------------------
// Kernel 1: per-block min/max partials of tv[:,:,2]. Plain stores, no init.
__global__ void __launch_bounds__(256) minmax_partial_kernel(const float* __restrict__ tv) {
    int i = blockIdx.x * blockDim.x + threadIdx.x;
    float z = (i < NV) ? __ldg(tv + 3 * i + 2) : __ldg(tv + 2);
    float mn = z, mx = z;
    #pragma unroll
    for (int o = 16; o > 0; o >>= 1) {
        mn = fminf(mn, __shfl_xor_sync(0xFFFFFFFFu, mn, o));
        mx = fmaxf(mx, __shfl_xor_sync(0xFFFFFFFFu, mx, o));
    }
    __shared__ float smn[8], smx[8];
    int lane = threadIdx.x & 31, w = threadIdx.x >> 5;
    if (lane == 0) { smn[w] = mn; smx[w] = mx; }
    __syncthreads();
    if (threadIdx.x == 0) {
        float bmn = smn[0], bmx = smx[0];
        #pragma unroll
        for (int k = 1; k < 8; k++) {
            bmn = fminf(bmn, smn[k]);
            bmx = fmaxf(bmx, smx[k]);
        }
        g_pmn[blockIdx.x] = bmn;
        g_pmx[blockIdx.x] = bmx;
    }
}

// ---------------------------------------------------------------------------
// Kernel 2: each block reduces the 314 partials (L2-hit), then builds the
// per-(image,face) 8B z table.
__global__ void __launch_bounds__(256) facez_kernel(const float* __restrict__ tv,
                                                    const int* __restrict__ faces) {
    float m = __int_as_float(0x7F800000);
    float M = -m;
    for (int k = threadIdx.x; k < MMBLK; k += 256) {
        m = fminf(m, g_pmn[k]);
        M = fmaxf(M, g_pmx[k]);
    }
    #pragma unroll
    for (int o = 16; o > 0; o >>= 1) {
        m = fminf(m, __shfl_xor_sync(0xFFFFFFFFu, m, o));
        M = fmaxf(M, __shfl_xor_sync(0xFFFFFFFFu, M, o));
    }
    __shared__ float smn[8], smx[8];
    __shared__ float s_m, s_R;
    int lane = threadIdx.x & 31, w = threadIdx.x >> 5;
    if (lane == 0) { smn[w] = m; smx[w] = M; }
    __syncthreads();
    if (threadIdx.x == 0) {
        float bm = smn[0], bM = smx[0];
        #pragma unroll
        for (int k = 1; k < 8; k++) {
            bm = fminf(bm, smn[k]);
            bM = fmaxf(bM, smx[k]);
        }
        s_m = bm;
        s_R = bM - bm;   // R = fl(M - m): reference rounding
    }
    __syncthreads();

    int t = blockIdx.x * blockDim.x + threadIdx.x;
    if (t >= NF) return;
    float m2 = s_m, R = s_R;
    int n = t / FF;
    int f = t - n * FF;
    int v0 = __ldg(faces + 3 * f);
    int v1 = __ldg(faces + 3 * f + 1);
    int v2 = __ldg(faces + 3 * f + 2);
    long long vb = (long long)n * VV;
    // zn = (R - fl(z - m)) / R  matches the reference rounding sequence
    float zn0 = (R - (__ldg(tv + 3 * (vb + v0) + 2) - m2)) / R;
    float zn1 = (R - (__ldg(tv + 3 * (vb + v1) + 2) - m2)) / R;
    float zn2 = (R - (__ldg(tv + 3 * (vb + v2) + 2) - m2)) / R;
    __half2 d = __floats2half2_rn(zn1 - zn0, zn2 - zn0);
    float2 e;
    e.x = zn0;
    e.y = __uint_as_float(*reinterpret_cast<unsigned int*>(&d));
    g_fz8[t] = e;
}

// ---------------------------------------------------------------------------
// Kernel 3: pixel interpolation. 4 px/thread (R3's proven TLP shape); all 4
// gathers are branch-free predicated LDGs issued before the streaming loads;
// streaming uses evict-first so the 1.25MB table keeps L1.
__global__ void __launch_bounds__(256) pixel_kernel(
    const float* __restrict__ bary,
    const int* __restrict__ p2f,
    float* __restrict__ out)
{
    int t = blockIdx.x * blockDim.x + threadIdx.x;
    long long base = (long long)t * 4;

    int4 pv = __ldcs(reinterpret_cast<const int4*>(p2f + base));
    int ps[4] = {pv.x, pv.y, pv.z, pv.w};

    // Branch-free predicated gathers, all issued up front (deep LSU queue).
    float2 e[4];
    #pragma unroll
    for (int i = 0; i < 4; i++)
        e[i] = gather_pred(g_fz8, ps[i], (int)(ps[i] >= 0));

    // 12 streaming bary floats (3x float4, evict-first).
    const float4* bp = reinterpret_cast<const float4*>(bary + base * 3);
    float4 b0 = __ldcs(bp);
    float4 b1 = __ldcs(bp + 1);
    float4 b2 = __ldcs(bp + 2);
    float w[12] = {b0.x, b0.y, b0.z, b0.w, b1.x, b1.y,
                   b1.z, b1.w, b2.x, b2.y, b2.z, b2.w};

    float res[4];
    #pragma unroll
    for (int i = 0; i < 4; i++) {
        float c0 = w[3 * i], c1 = w[3 * i + 1], c2 = w[3 * i + 2];
        unsigned int db = __float_as_uint(e[i].y);
        __half2 dh = *reinterpret_cast<__half2*>(&db);
        float2 d = __half22float2(dh);
        float s = e[i].x * (c0 + c1 + c2) + c1 * d.x + c2 * d.y;
        res[i] = ps[i] >= 0 ? s : 0.0f;
    }

    __stcs(reinterpret_cast<float4*>(out + base),
           make_float4(res[0], res[1], res[2], res[3]));
}

extern "C" void kernel_launch(void* const* d_in, const int* in_sizes, int n_in,
                              void* d_out, int out_size) {
    const float* tv = nullptr;      // 241104
    const float* bary = nullptr;    // 12582912
    const int* faces = nullptr;     // 29928
    const int* p2f = nullptr;       // 4194304
    for (int i = 0; i < n_in; i++) {
        switch (in_sizes[i]) {
            case NN * VV * 3:            tv    = (const float*)d_in[i]; break;
            case NN * HH * WW * 3:       bary  = (const float*)d_in[i]; break;
            case FF * 3:                 faces = (const int*)d_in[i];   break;
            case NN * HH * WW:           p2f   = (const int*)d_in[i];   break;
        }
    }
    float* out = (float*)d_out;

    minmax_partial_kernel<<<MMBLK, 256>>>(tv);
    facez_kernel<<<(NF + 255) / 256, 256>>>(tv, faces);
    pixel_kernel<<<NPIX / 4 / 256, 256>>>(bary, p2f, out);
}

// round 9
// speedup vs baseline: 1.3210x; 1.0240x over previous
#include <cuda_runtime.h>
#include <cuda_fp16.h>

#define NN 16
#define VV 5023
#define FF 9976
#define HH 512
#define WW 512
#define NV (NN * VV)            // 80368
#define NF (NN * FF)            // 159616
#define NPIX (NN * HH * WW)     // 4194304
#define MMBLK 314               // blocks that produce minmax partials
#define K1GRID ((NF + 255) / 256)   // 624

__device__ float g_pmn[MMBLK];
__device__ float g_pmx[MMBLK];
__device__ float2 g_mR;         // {m, 1/R}
__device__ int g_done;          // zero-init; self-resets each run
__device__ float2 g_fz8[NF];    // 8B/(image,face): z0 fp32 (raw) + (z1-z0,z2-z0) fp16x2 (raw)

// Branch-free predicated 8B gather: single @p LDG.E.64.NC, no BSSY/BSYNC.
__device__ __forceinline__ float2 gather_pred(const float2* __restrict__ tab,
                                              int idx, int valid) {
    float2 r;
    const float2* addr = tab + (valid ? idx : 0);
    asm("{\n\t"
        ".reg .pred gp;\n\t"
        "setp.ne.s32 gp, %3, 0;\n\t"
        "mov.f32 %0, 0f00000000;\n\t"
        "mov.f32 %1, 0f00000000;\n\t"
        "@gp ld.global.nc.v2.f32 {%0,%1}, [%2];\n\t"
        "}"
        : "=f"(r.x), "=f"(r.y)
        : "l"(addr), "r"(valid));
    return r;
}

// ---------------------------------------------------------------------------
// Kernel 1: builds the RAW face-z table (independent of min/max!) and, in the
// same launch, computes min/max partials; the last-finished partial block
// reduces them to g_mR = {m, 1/R}. One launch replaces minmax+facez.
__global__ void __launch_bounds__(256) prep_kernel(const float* __restrict__ tv,
                                                   const int* __restrict__ faces) {
    const int tid = threadIdx.x;
    const int t = blockIdx.x * 256 + tid;
    __shared__ float smn[8], smx[8];
    __shared__ int is_last;

    // ---- raw face table: {z0, (z1-z0, z2-z0) fp16x2} -----------------------
    if (t < NF) {
        int n = t / FF;
        int f = t - n * FF;
        int v0 = __ldg(faces + 3 * f);
        int v1 = __ldg(faces + 3 * f + 1);
        int v2 = __ldg(faces + 3 * f + 2);
        long long vb = (long long)n * VV;
        float z0 = __ldg(tv + 3 * (vb + v0) + 2);
        float z1 = __ldg(tv + 3 * (vb + v1) + 2);
        float z2 = __ldg(tv + 3 * (vb + v2) + 2);
        __half2 d = __floats2half2_rn(z1 - z0, z2 - z0);
        float2 e;
        e.x = z0;
        e.y = __uint_as_float(*reinterpret_cast<unsigned int*>(&d));
        g_fz8[t] = e;
    }

    // ---- min/max partials over tv[:,:,2] (first MMBLK blocks only) ---------
    if (blockIdx.x < MMBLK) {
        float z = (t < NV) ? __ldg(tv + 3 * t + 2) : __ldg(tv + 2);
        float mn = z, mx = z;
        #pragma unroll
        for (int o = 16; o > 0; o >>= 1) {
            mn = fminf(mn, __shfl_xor_sync(0xFFFFFFFFu, mn, o));
            mx = fmaxf(mx, __shfl_xor_sync(0xFFFFFFFFu, mx, o));
        }
        int lane = tid & 31, w = tid >> 5;
        if (lane == 0) { smn[w] = mn; smx[w] = mx; }
        __syncthreads();
        if (tid == 0) {
            float bmn = smn[0], bmx = smx[0];
            #pragma unroll
            for (int k = 1; k < 8; k++) {
                bmn = fminf(bmn, smn[k]);
                bmx = fmaxf(bmx, smx[k]);
            }
            g_pmn[blockIdx.x] = bmn;
            g_pmx[blockIdx.x] = bmx;
            __threadfence();
            int c = atomicAdd(&g_done, 1);
            is_last = (c == MMBLK - 1);
        }
        __syncthreads();

        // Last-done block reduces the 314 partials (deterministic order).
        if (is_last) {
            float m = __int_as_float(0x7F800000);
            float M = -m;
            for (int k = tid; k < MMBLK; k += 256) {
                m = fminf(m, g_pmn[k]);
                M = fmaxf(M, g_pmx[k]);
            }
            #pragma unroll
            for (int o = 16; o > 0; o >>= 1) {
                m = fminf(m, __shfl_xor_sync(0xFFFFFFFFu, m, o));
                M = fmaxf(M, __shfl_xor_sync(0xFFFFFFFFu, M, o));
            }
            int lane = tid & 31, w = tid >> 5;
            if (lane == 0) { smn[w] = m; smx[w] = M; }
            __syncthreads();
            if (tid == 0) {
                float bm = smn[0], bM = smx[0];
                #pragma unroll
                for (int k = 1; k < 8; k++) {
                    bm = fminf(bm, smn[k]);
                    bM = fmaxf(bM, smx[k]);
                }
                float R = bM - bm;           // R = fl(M - m)
                g_mR = make_float2(bm, 1.0f / R);
                g_done = 0;                  // reset for next graph replay
            }
        }
    }
}

// ---------------------------------------------------------------------------
// Kernel 2: pixel interpolation. 4 px/thread; branch-free predicated 8B
// gathers issued before the streaming loads; streaming evict-first.
// s = 1 - (z0 - m + b1*d1 + b2*d2) / R   (valid), 0 (invalid).
__global__ void __launch_bounds__(256) pixel_kernel(
    const float* __restrict__ bary,
    const int* __restrict__ p2f,
    float* __restrict__ out)
{
    int t = blockIdx.x * blockDim.x + threadIdx.x;
    long long base = (long long)t * 4;

    int4 pv = __ldcs(reinterpret_cast<const int4*>(p2f + base));
    int ps[4] = {pv.x, pv.y, pv.z, pv.w};

    // All 4 gathers issued up front (deep LSU queue).
    float2 e[4];
    #pragma unroll
    for (int i = 0; i < 4; i++)
        e[i] = gather_pred(g_fz8, ps[i], (int)(ps[i] >= 0));

    const float4* bp = reinterpret_cast<const float4*>(bary + base * 3);
    float4 b0 = __ldcs(bp);
    float4 b1 = __ldcs(bp + 1);
    float4 b2 = __ldcs(bp + 2);
    float w[12] = {b0.x, b0.y, b0.z, b0.w, b1.x, b1.y,
                   b1.z, b1.w, b2.x, b2.y, b2.z, b2.w};

    float2 mR = g_mR;          // uniform, L1-hit
    float m = mR.x, rcpR = mR.y;

    float res[4];
    #pragma unroll
    for (int i = 0; i < 4; i++) {
        float c1 = w[3 * i + 1], c2 = w[3 * i + 2];
        unsigned int db = __float_as_uint(e[i].y);
        __half2 dh = *reinterpret_cast<__half2*>(&db);
        float2 d = __half22float2(dh);
        float zbar = e[i].x - m + c1 * d.x + c2 * d.y;   // Σb·z - m (raw)
        float s = 1.0f - zbar * rcpR;
        res[i] = ps[i] >= 0 ? s : 0.0f;
    }

    __stcs(reinterpret_cast<float4*>(out + base),
           make_float4(res[0], res[1], res[2], res[3]));
}

extern "C" void kernel_launch(void* const* d_in, const int* in_sizes, int n_in,
                              void* d_out, int out_size) {
    const float* tv = nullptr;      // 241104
    const float* bary = nullptr;    // 12582912
    const int* faces = nullptr;     // 29928
    const int* p2f = nullptr;       // 4194304
    for (int i = 0; i < n_in; i++) {
        switch (in_sizes[i]) {
            case NN * VV * 3:            tv    = (const float*)d_in[i]; break;
            case NN * HH * WW * 3:       bary  = (const float*)d_in[i]; break;
            case FF * 3:                 faces = (const int*)d_in[i];   break;
            case NN * HH * WW:           p2f   = (const int*)d_in[i];   break;
        }
    }
    float* out = (float*)d_out;

    prep_kernel<<<K1GRID, 256>>>(tv, faces);
    pixel_kernel<<<NPIX / 4 / 256, 256>>>(bary, p2f, out);
}